// round 3
// baseline (speedup 1.0000x reference)
#include <cuda_runtime.h>
#include <math.h>

#define T_TOTAL 65536
#define T_BATCH 8192
#define CH 256
#define CH2 512
#define MEL 640

#define BM 64
#define BN 64
#define BK 16

// Scratch (allocation-free rule: __device__ globals)
__device__ float g_h[(size_t)T_TOTAL * CH];
__device__ float g_acts[(size_t)T_TOTAL * CH];
__device__ float g_skip[(size_t)T_TOTAL * CH];

// ---------------------------------------------------------------------------
// start: h = audio @ start_w + start_b ; skip = 0
// ---------------------------------------------------------------------------
__global__ void start_kernel(const float* __restrict__ audio,
                             const float* __restrict__ sw,
                             const float* __restrict__ sb) {
    int idx = blockIdx.x * blockDim.x + threadIdx.x;   // 16,777,216 total
    int t = idx >> 8;
    int c = idx & 255;
    float4 a = *(const float4*)&audio[(size_t)t * 4];
    float v = sb[c] + a.x * sw[c] + a.y * sw[256 + c] + a.z * sw[512 + c] + a.w * sw[768 + c];
    g_h[idx] = v;
    g_skip[idx] = 0.f;
}

// ---------------------------------------------------------------------------
// layer A: x = dilated_conv(h) + spect@cond_w + biases; acts = tanh(xa)*sig(xb)
// GEMM over concatenated K = 3*256 (taps) + 640 (cond) = 1408
// Each thread computes 4x4 outputs for BOTH gate halves (j and j+256).
// ---------------------------------------------------------------------------
__global__ void __launch_bounds__(256) layerA_kernel(
    const float* __restrict__ in_w,    // [3,256,512] layer slice
    const float* __restrict__ in_b,    // [512]
    const float* __restrict__ cond_w,  // [640,512] layer slice
    const float* __restrict__ cond_b,  // [512]
    const float* __restrict__ spect,   // [65536,640]
    int dil) {
    __shared__ float As[BK][BM + 4];   // transposed [k][m], pad to stride 68
    __shared__ float Bs0[BK][BN];
    __shared__ float Bs1[BK][BN];

    const int tid = threadIdx.x;
    const int row0 = blockIdx.x * BM;
    const int n0 = blockIdx.y * BN;

    const int a_r = tid >> 2;         // 0..63  (m row loaded)
    const int a_c = (tid & 3) * 4;    // 0,4,8,12 (k offset within chunk)
    const int b_r = tid >> 4;         // 0..15 (k row)
    const int b_c = (tid & 15) * 4;   // 0..60 (n offset)

    const int ty = tid >> 4;          // 0..15 -> rows ty*4..ty*4+3
    const int tx = tid & 15;          // 0..15 -> cols tx*4..tx*4+3

    float acc0[4][4] = {};
    float acc1[4][4] = {};

    const int r = row0 + a_r;
    const int tl = r & (T_BATCH - 1);

    const float* Asp = &As[0][ty * 4];
    const float* Bs0p = &Bs0[0][tx * 4];
    const float* Bs1p = &Bs1[0][tx * 4];

    for (int kt = 0; kt < 88; kt++) {
        const int kk0 = kt * BK;
        float4 av;
        const float* wb;
        int wrow;
        if (kk0 < 768) {
            // dilated conv tap segment
            const int tap = kk0 >> 8;            // 0,1,2
            const int kc = kk0 - (tap << 8);     // 0..240
            const int shift = (tap - 1) * dil;
            const int ts = tl + shift;
            if ((unsigned)ts < (unsigned)T_BATCH) {
                av = *(const float4*)&g_h[(size_t)(r + shift) * CH + kc + a_c];
            } else {
                av = make_float4(0.f, 0.f, 0.f, 0.f);
            }
            wb = in_w + (size_t)tap * CH * CH2;
            wrow = kc + b_r;
        } else {
            // conditioning segment
            const int km = kk0 - 768;
            av = *(const float4*)&spect[(size_t)r * MEL + km + a_c];
            wb = cond_w;
            wrow = km + b_r;
        }
        float4 bv0 = *(const float4*)&wb[(size_t)wrow * CH2 + n0 + b_c];
        float4 bv1 = *(const float4*)&wb[(size_t)wrow * CH2 + n0 + 256 + b_c];

        As[a_c + 0][a_r] = av.x;
        As[a_c + 1][a_r] = av.y;
        As[a_c + 2][a_r] = av.z;
        As[a_c + 3][a_r] = av.w;
        *(float4*)&Bs0[b_r][b_c] = bv0;
        *(float4*)&Bs1[b_r][b_c] = bv1;
        __syncthreads();

        #pragma unroll
        for (int k = 0; k < BK; k++) {
            float4 a4 = *(const float4*)&Asp[k * (BM + 4)];
            float4 b4 = *(const float4*)&Bs0p[k * BN];
            float4 c4 = *(const float4*)&Bs1p[k * BN];
            float am[4] = {a4.x, a4.y, a4.z, a4.w};
            float bm0[4] = {b4.x, b4.y, b4.z, b4.w};
            float bm1[4] = {c4.x, c4.y, c4.z, c4.w};
            #pragma unroll
            for (int q = 0; q < 4; q++) {
                #pragma unroll
                for (int rr = 0; rr < 4; rr++) {
                    acc0[q][rr] += am[q] * bm0[rr];
                    acc1[q][rr] += am[q] * bm1[rr];
                }
            }
        }
        __syncthreads();
    }

    #pragma unroll
    for (int q = 0; q < 4; q++) {
        const int m = row0 + ty * 4 + q;
        #pragma unroll
        for (int rr = 0; rr < 4; rr++) {
            const int j = n0 + tx * 4 + rr;
            float xa = acc0[q][rr] + in_b[j] + cond_b[j];
            float xb = acc1[q][rr] + in_b[j + 256] + cond_b[j + 256];
            float tnh = tanhf(xa);
            float sg = 1.f / (1.f + expf(-xb));
            g_acts[(size_t)m * CH + j] = tnh * sg;
        }
    }
}

// ---------------------------------------------------------------------------
// layer B (i < 7): rs = acts @ res_skip_w + b ; h += rs[:,:256]; skip += rs[:,256:]
// ---------------------------------------------------------------------------
__global__ void __launch_bounds__(256) layerB_kernel(
    const float* __restrict__ w,   // [256,512] layer slice
    const float* __restrict__ b) { // [512]
    __shared__ float As[BK][BM + 4];
    __shared__ float Bs0[BK][BN];
    __shared__ float Bs1[BK][BN];

    const int tid = threadIdx.x;
    const int row0 = blockIdx.x * BM;
    const int n0 = blockIdx.y * BN;

    const int a_r = tid >> 2;
    const int a_c = (tid & 3) * 4;
    const int b_r = tid >> 4;
    const int b_c = (tid & 15) * 4;
    const int ty = tid >> 4;
    const int tx = tid & 15;

    float acc0[4][4] = {};
    float acc1[4][4] = {};

    const int r = row0 + a_r;

    const float* Asp = &As[0][ty * 4];
    const float* Bs0p = &Bs0[0][tx * 4];
    const float* Bs1p = &Bs1[0][tx * 4];

    #pragma unroll 4
    for (int kt = 0; kt < CH / BK; kt++) {
        const int kk0 = kt * BK;
        float4 av = *(const float4*)&g_acts[(size_t)r * CH + kk0 + a_c];
        float4 bv0 = *(const float4*)&w[(size_t)(kk0 + b_r) * CH2 + n0 + b_c];
        float4 bv1 = *(const float4*)&w[(size_t)(kk0 + b_r) * CH2 + n0 + 256 + b_c];

        As[a_c + 0][a_r] = av.x;
        As[a_c + 1][a_r] = av.y;
        As[a_c + 2][a_r] = av.z;
        As[a_c + 3][a_r] = av.w;
        *(float4*)&Bs0[b_r][b_c] = bv0;
        *(float4*)&Bs1[b_r][b_c] = bv1;
        __syncthreads();

        #pragma unroll
        for (int k = 0; k < BK; k++) {
            float4 a4 = *(const float4*)&Asp[k * (BM + 4)];
            float4 b4 = *(const float4*)&Bs0p[k * BN];
            float4 c4 = *(const float4*)&Bs1p[k * BN];
            float am[4] = {a4.x, a4.y, a4.z, a4.w};
            float bm0[4] = {b4.x, b4.y, b4.z, b4.w};
            float bm1[4] = {c4.x, c4.y, c4.z, c4.w};
            #pragma unroll
            for (int q = 0; q < 4; q++) {
                #pragma unroll
                for (int rr = 0; rr < 4; rr++) {
                    acc0[q][rr] += am[q] * bm0[rr];
                    acc1[q][rr] += am[q] * bm1[rr];
                }
            }
        }
        __syncthreads();
    }

    #pragma unroll
    for (int q = 0; q < 4; q++) {
        const int m = row0 + ty * 4 + q;
        #pragma unroll
        for (int rr = 0; rr < 4; rr++) {
            const int j = n0 + tx * 4 + rr;
            g_h[(size_t)m * CH + j]   += acc0[q][rr] + b[j];
            g_skip[(size_t)m * CH + j] += acc1[q][rr] + b[j + 256];
        }
    }
}

// ---------------------------------------------------------------------------
// last layer: skip += acts @ res_last_w + res_last_b   (256 -> 256)
// ---------------------------------------------------------------------------
__global__ void __launch_bounds__(256) layerLast_kernel(
    const float* __restrict__ w,   // [256,256]
    const float* __restrict__ b) { // [256]
    __shared__ float As[BK][BM + 4];
    __shared__ float Bs0[BK][BN];

    const int tid = threadIdx.x;
    const int row0 = blockIdx.x * BM;
    const int n0 = blockIdx.y * BN;

    const int a_r = tid >> 2;
    const int a_c = (tid & 3) * 4;
    const int b_r = tid >> 4;
    const int b_c = (tid & 15) * 4;
    const int ty = tid >> 4;
    const int tx = tid & 15;

    float acc0[4][4] = {};
    const int r = row0 + a_r;

    const float* Asp = &As[0][ty * 4];
    const float* Bs0p = &Bs0[0][tx * 4];

    #pragma unroll 4
    for (int kt = 0; kt < CH / BK; kt++) {
        const int kk0 = kt * BK;
        float4 av = *(const float4*)&g_acts[(size_t)r * CH + kk0 + a_c];
        float4 bv0 = *(const float4*)&w[(size_t)(kk0 + b_r) * CH + n0 + b_c];

        As[a_c + 0][a_r] = av.x;
        As[a_c + 1][a_r] = av.y;
        As[a_c + 2][a_r] = av.z;
        As[a_c + 3][a_r] = av.w;
        *(float4*)&Bs0[b_r][b_c] = bv0;
        __syncthreads();

        #pragma unroll
        for (int k = 0; k < BK; k++) {
            float4 a4 = *(const float4*)&Asp[k * (BM + 4)];
            float4 b4 = *(const float4*)&Bs0p[k * BN];
            float am[4] = {a4.x, a4.y, a4.z, a4.w};
            float bm0[4] = {b4.x, b4.y, b4.z, b4.w};
            #pragma unroll
            for (int q = 0; q < 4; q++) {
                #pragma unroll
                for (int rr = 0; rr < 4; rr++) {
                    acc0[q][rr] += am[q] * bm0[rr];
                }
            }
        }
        __syncthreads();
    }

    #pragma unroll
    for (int q = 0; q < 4; q++) {
        const int m = row0 + ty * 4 + q;
        #pragma unroll
        for (int rr = 0; rr < 4; rr++) {
            const int j = n0 + tx * 4 + rr;
            g_skip[(size_t)m * CH + j] += acc0[q][rr] + b[j];
        }
    }
}

// ---------------------------------------------------------------------------
// end: out = skip @ end_w + end_b   (256 -> 8)
// ---------------------------------------------------------------------------
__global__ void end_kernel(const float* __restrict__ ew,
                           const float* __restrict__ eb,
                           float* __restrict__ out) {
    int idx = blockIdx.x * blockDim.x + threadIdx.x;   // 524288
    int t = idx >> 3;
    int o = idx & 7;
    const float* s = &g_skip[(size_t)t * CH];
    float acc = eb[o];
    #pragma unroll 4
    for (int c = 0; c < CH; c++) acc += s[c] * ew[c * 8 + o];
    out[idx] = acc;
}

// ---------------------------------------------------------------------------
extern "C" void kernel_launch(void* const* d_in, const int* in_sizes, int n_in,
                              void* d_out, int out_size) {
    const float* audio      = (const float*)d_in[0];
    const float* spect      = (const float*)d_in[1];
    const float* start_w    = (const float*)d_in[2];
    const float* start_b    = (const float*)d_in[3];
    const float* in_w       = (const float*)d_in[4];
    const float* in_b       = (const float*)d_in[5];
    const float* cond_w     = (const float*)d_in[6];
    const float* cond_b     = (const float*)d_in[7];
    const float* res_skip_w = (const float*)d_in[8];
    const float* res_skip_b = (const float*)d_in[9];
    const float* res_last_w = (const float*)d_in[10];
    const float* res_last_b = (const float*)d_in[11];
    const float* end_w      = (const float*)d_in[12];
    const float* end_b      = (const float*)d_in[13];
    float* out = (float*)d_out;

    start_kernel<<<(T_TOTAL * CH) / 256, 256>>>(audio, start_w, start_b);

    dim3 gA(T_TOTAL / BM, 256 / BN);   // (1024, 4)
    for (int i = 0; i < 8; i++) {
        int dil = 1 << i;
        layerA_kernel<<<gA, 256>>>(in_w + (size_t)i * 3 * CH * CH2,
                                   in_b + (size_t)i * CH2,
                                   cond_w + (size_t)i * MEL * CH2,
                                   cond_b + (size_t)i * CH2,
                                   spect, dil);
        if (i < 7) {
            layerB_kernel<<<gA, 256>>>(res_skip_w + (size_t)i * CH * CH2,
                                       res_skip_b + (size_t)i * CH2);
        } else {
            layerLast_kernel<<<gA, 256>>>(res_last_w, res_last_b);
        }
    }

    end_kernel<<<(T_TOTAL * 8) / 256, 256>>>(end_w, end_b, out);
}

// round 5
// speedup vs baseline: 3.5283x; 3.5283x over previous
#include <cuda_runtime.h>
#include <cstdint>
#include <math.h>

#define T_TOTAL 65536
#define T_BATCH 8192
#define CH 256
#define MEL 640

// ---------------- scratch (__device__ globals) ------------------------------
__device__ float g_h[(size_t)T_TOTAL * CH];      // fp32 residual
__device__ float g_hT[(size_t)T_TOTAL * CH];     // tf32-rounded shadow of h
__device__ float g_acts[(size_t)T_TOTAL * CH];   // tf32-rounded
__device__ float g_skip[(size_t)T_TOTAL * CH];   // fp32
__device__ float g_spectT[(size_t)T_TOTAL * MEL];// tf32-rounded spect
__device__ float g_wTA[(size_t)8 * 512 * 1408];  // [layer][n][k] tf32
__device__ float g_wTB[(size_t)7 * 512 * 256];   // [layer][n][k] tf32
__device__ float g_wTL[(size_t)256 * 256];       // [n][k] tf32

// ---------------- helpers ---------------------------------------------------
__device__ __forceinline__ uint32_t smem_u32(const void* p) {
    uint32_t a;
    asm("{ .reg .u64 t; cvta.to.shared.u64 t, %1; cvt.u32.u64 %0, t; }" : "=r"(a) : "l"(p));
    return a;
}
__device__ __forceinline__ uint32_t f2tf(float x) {
    uint32_t r; asm("cvt.rna.tf32.f32 %0, %1;" : "=r"(r) : "f"(x)); return r;
}
__device__ __forceinline__ float rtf(float x) { return __uint_as_float(f2tf(x)); }

#define CP16(dst, src, sz) \
    asm volatile("cp.async.cg.shared.global [%0], [%1], 16, %2;" \
        :: "r"(dst), "l"(src), "r"(sz) : "memory")
#define CP_COMMIT() asm volatile("cp.async.commit_group;" ::: "memory")
#define CP_WAIT(n)  asm volatile("cp.async.wait_group %0;" :: "n"(n) : "memory")

__device__ __forceinline__ void mma8(float* d, const uint32_t* a, const uint32_t* b) {
    asm volatile(
        "mma.sync.aligned.m16n8k8.row.col.f32.tf32.tf32.f32 "
        "{%0,%1,%2,%3}, {%4,%5,%6,%7}, {%8,%9}, {%0,%1,%2,%3};"
        : "+f"(d[0]), "+f"(d[1]), "+f"(d[2]), "+f"(d[3])
        : "r"(a[0]), "r"(a[1]), "r"(a[2]), "r"(a[3]), "r"(b[0]), "r"(b[1]));
}

// ---------------- smem layout (bytes) ---------------------------------------
// A/B tiles: 128 rows x 32 k fp32, row stride 36 floats (144 B) -> 18432 B
#define AST 36
#define OFF_A(buf) ((buf) * 36864)
#define OFF_B(buf) (18432 + (buf) * 36864)
#define OFF_BIAS   73728
#define SMEM_SZ    75776

// ---------------------------------------------------------------------------
// start: h = audio @ start_w + start_b ; hT = tf32(h) ; skip = 0
// ---------------------------------------------------------------------------
__global__ void start_kernel(const float* __restrict__ audio,
                             const float* __restrict__ sw,
                             const float* __restrict__ sb) {
    int idx = blockIdx.x * blockDim.x + threadIdx.x;
    int t = idx >> 8;
    int c = idx & 255;
    float4 a = *(const float4*)&audio[(size_t)t * 4];
    float v = sb[c] + a.x * sw[c] + a.y * sw[256 + c] + a.z * sw[512 + c] + a.w * sw[768 + c];
    g_h[idx] = v;
    g_hT[idx] = rtf(v);
    g_skip[idx] = 0.f;
}

__global__ void round_spect_kernel(const float* __restrict__ spect) {
    size_t idx = (size_t)blockIdx.x * blockDim.x + threadIdx.x;
    g_spectT[idx] = rtf(spect[idx]);
}

// weight transposes: [k][n] -> [n][k], tf32-rounded
__global__ void transA_kernel(const float* __restrict__ in_w, const float* __restrict__ cond_w) {
    size_t idx = (size_t)blockIdx.x * blockDim.x + threadIdx.x;   // 8*512*1408
    int k = (int)(idx % 1408);
    size_t t = idx / 1408;
    int n = (int)(t % 512);
    int l = (int)(t / 512);
    float v;
    if (k < 768)
        v = in_w[(((size_t)l * 3 + (k >> 8)) * 256 + (k & 255)) * 512 + n];
    else
        v = cond_w[((size_t)l * 640 + (k - 768)) * 512 + n];
    g_wTA[idx] = rtf(v);
}
__global__ void transB_kernel(const float* __restrict__ rsw) {
    size_t idx = (size_t)blockIdx.x * blockDim.x + threadIdx.x;   // 7*512*256
    int k = (int)(idx & 255);
    size_t t = idx >> 8;
    int n = (int)(t % 512);
    int l = (int)(t / 512);
    g_wTB[idx] = rtf(rsw[((size_t)l * 256 + k) * 512 + n]);
}
__global__ void transL_kernel(const float* __restrict__ rlw) {
    int idx = blockIdx.x * blockDim.x + threadIdx.x;              // 256*256
    int k = idx & 255;
    int n = idx >> 8;
    g_wTL[idx] = rtf(rlw[k * 256 + n]);
}

// ---------------------------------------------------------------------------
// GEMM compute body: warp computes 32x32 per half via m16n8k8 tf32 mma
// As: [m 0..127][k 0..31] stride 36 ; Bs: [n 0..127][k 0..31] stride 36
// ---------------------------------------------------------------------------
__device__ __forceinline__ void compute_stage(const float* As, const float* Bs,
                                              int wm, int wn, int lane,
                                              float d[2][2][4][4], int nhalves) {
    const int ar = lane >> 2;
    const int ac = lane & 3;
    #pragma unroll
    for (int q = 0; q < 4; q++) {
        const int k0 = q * 8;
        uint32_t a[2][4];
        #pragma unroll
        for (int mi = 0; mi < 2; mi++) {
            int mb = wm * 32 + mi * 16 + ar;
            a[mi][0] = __float_as_uint(As[mb * AST + k0 + ac]);
            a[mi][1] = __float_as_uint(As[(mb + 8) * AST + k0 + ac]);
            a[mi][2] = __float_as_uint(As[mb * AST + k0 + ac + 4]);
            a[mi][3] = __float_as_uint(As[(mb + 8) * AST + k0 + ac + 4]);
        }
        #pragma unroll
        for (int t = 0; t < 2; t++) {
            if (t >= nhalves) break;
            #pragma unroll
            for (int ni = 0; ni < 4; ni++) {
                int nb = t * 64 + wn * 32 + ni * 8 + ar;
                uint32_t b[2];
                b[0] = __float_as_uint(Bs[nb * AST + k0 + ac]);
                b[1] = __float_as_uint(Bs[nb * AST + k0 + ac + 4]);
                mma8(d[t][0][ni], a[0], b);
                mma8(d[t][1][ni], a[1], b);
            }
        }
    }
}

// ---------------------------------------------------------------------------
// layer A: x = conv(h)+cond+biases ; acts = tf32(tanh(xa)*sigmoid(xb))
// ---------------------------------------------------------------------------
__global__ void __launch_bounds__(256, 2) layerA_mma(
    const float* __restrict__ in_b, const float* __restrict__ cond_b,
    int layer, int dil) {
    extern __shared__ char smem[];
    const uint32_t sbase = smem_u32(smem);
    const int tid = threadIdx.x;
    const int lane = tid & 31;
    const int wid = tid >> 5;
    const int wm = wid & 3;
    const int wn = wid >> 2;
    const int row0 = blockIdx.x * 128;
    const int n0 = blockIdx.y * 64;
    const float* __restrict__ wT = g_wTA + (size_t)layer * 512 * 1408;

    {   // biases
        float* bsm = (float*)(smem + OFF_BIAS);
        bsm[tid] = in_b[layer * 512 + tid] + cond_b[layer * 512 + tid];
        bsm[256 + tid] = in_b[layer * 512 + 256 + tid] + cond_b[layer * 512 + 256 + tid];
    }

    const int lrow = tid >> 3;       // 0..31 rows per pass? no: chunk id
    // staging: 1024 chunks (A) + 1024 (B) of 16B; thread does 4+4
    auto load_stage = [&](int s, int buf) {
        const int kk0 = s * 32;
        const uint32_t abase = sbase + OFF_A(buf);
        const uint32_t bbase = sbase + OFF_B(buf);
        if (kk0 < 768) {
            const int tap = kk0 >> 8, kc = kk0 & 255;
            const int shift = (tap - 1) * dil;
            #pragma unroll
            for (int i = 0; i < 4; i++) {
                int v = tid + i * 256;
                int row = v >> 3, c8 = v & 7;
                int r = row0 + row;
                int ts = (r & (T_BATCH - 1)) + shift;
                const float* src;
                uint32_t sz;
                if ((unsigned)ts < (unsigned)T_BATCH) {
                    src = g_hT + (size_t)(r + shift) * CH + kc + c8 * 4;
                    sz = 16;
                } else {
                    src = g_hT;
                    sz = 0;
                }
                CP16(abase + row * 144 + c8 * 16, src, sz);
            }
        } else {
            const int km = kk0 - 768;
            #pragma unroll
            for (int i = 0; i < 4; i++) {
                int v = tid + i * 256;
                int row = v >> 3, c8 = v & 7;
                const float* src = g_spectT + (size_t)(row0 + row) * MEL + km + c8 * 4;
                CP16(abase + row * 144 + c8 * 16, src, 16);
            }
        }
        #pragma unroll
        for (int i = 0; i < 4; i++) {
            int v = tid + i * 256;
            int nl = v >> 3, c8 = v & 7;
            int ng = (nl < 64) ? (n0 + nl) : (n0 + 256 + nl - 64);
            const float* src = wT + (size_t)ng * 1408 + kk0 + c8 * 4;
            CP16(bbase + nl * 144 + c8 * 16, src, 16);
        }
        CP_COMMIT();
    };

    float d[2][2][4][4] = {};

    load_stage(0, 0);
    for (int s = 0; s < 44; s++) {
        if (s + 1 < 44) { load_stage(s + 1, (s + 1) & 1); CP_WAIT(1); }
        else CP_WAIT(0);
        __syncthreads();
        compute_stage((const float*)(smem + OFF_A(s & 1)),
                      (const float*)(smem + OFF_B(s & 1)), wm, wn, lane, d, 2);
        __syncthreads();
    }

    const float* bsm = (const float*)(smem + OFF_BIAS);
    #pragma unroll
    for (int mi = 0; mi < 2; mi++) {
        #pragma unroll
        for (int eh = 0; eh < 2; eh++) {
            const int m = row0 + wm * 32 + mi * 16 + (lane >> 2) + eh * 8;
            #pragma unroll
            for (int ni = 0; ni < 4; ni++) {
                const int j = n0 + wn * 32 + ni * 8 + (lane & 3) * 2;
                float xa0 = d[0][mi][ni][eh * 2 + 0] + bsm[j];
                float xa1 = d[0][mi][ni][eh * 2 + 1] + bsm[j + 1];
                float xb0 = d[1][mi][ni][eh * 2 + 0] + bsm[256 + j];
                float xb1 = d[1][mi][ni][eh * 2 + 1] + bsm[256 + j + 1];
                float2 o;
                o.x = rtf(tanhf(xa0) * (1.f / (1.f + expf(-xb0))));
                o.y = rtf(tanhf(xa1) * (1.f / (1.f + expf(-xb1))));
                *(float2*)&g_acts[(size_t)m * CH + j] = o;
            }
        }
    }
}

// ---------------------------------------------------------------------------
// layer B: rs = acts@w + b ; h += rs[:, :256] (fp32 + tf32 shadow); skip += rs[:, 256:]
// ---------------------------------------------------------------------------
__global__ void __launch_bounds__(256, 2) layerB_mma(
    const float* __restrict__ rs_b, int layer) {
    extern __shared__ char smem[];
    const uint32_t sbase = smem_u32(smem);
    const int tid = threadIdx.x;
    const int lane = tid & 31;
    const int wid = tid >> 5;
    const int wm = wid & 3;
    const int wn = wid >> 2;
    const int row0 = blockIdx.x * 128;
    const int n0 = blockIdx.y * 64;
    const float* __restrict__ wT = g_wTB + (size_t)layer * 512 * 256;

    {
        float* bsm = (float*)(smem + OFF_BIAS);
        bsm[tid] = rs_b[layer * 512 + tid];
        bsm[256 + tid] = rs_b[layer * 512 + 256 + tid];
    }

    auto load_stage = [&](int s, int buf) {
        const int kk0 = s * 32;
        const uint32_t abase = sbase + OFF_A(buf);
        const uint32_t bbase = sbase + OFF_B(buf);
        #pragma unroll
        for (int i = 0; i < 4; i++) {
            int v = tid + i * 256;
            int row = v >> 3, c8 = v & 7;
            const float* src = g_acts + (size_t)(row0 + row) * CH + kk0 + c8 * 4;
            CP16(abase + row * 144 + c8 * 16, src, 16);
        }
        #pragma unroll
        for (int i = 0; i < 4; i++) {
            int v = tid + i * 256;
            int nl = v >> 3, c8 = v & 7;
            int ng = (nl < 64) ? (n0 + nl) : (n0 + 256 + nl - 64);
            const float* src = wT + (size_t)ng * 256 + kk0 + c8 * 4;
            CP16(bbase + nl * 144 + c8 * 16, src, 16);
        }
        CP_COMMIT();
    };

    float d[2][2][4][4] = {};

    load_stage(0, 0);
    for (int s = 0; s < 8; s++) {
        if (s + 1 < 8) { load_stage(s + 1, (s + 1) & 1); CP_WAIT(1); }
        else CP_WAIT(0);
        __syncthreads();
        compute_stage((const float*)(smem + OFF_A(s & 1)),
                      (const float*)(smem + OFF_B(s & 1)), wm, wn, lane, d, 2);
        __syncthreads();
    }

    const float* bsm = (const float*)(smem + OFF_BIAS);
    #pragma unroll
    for (int mi = 0; mi < 2; mi++) {
        #pragma unroll
        for (int eh = 0; eh < 2; eh++) {
            const int m = row0 + wm * 32 + mi * 16 + (lane >> 2) + eh * 8;
            #pragma unroll
            for (int ni = 0; ni < 4; ni++) {
                const int j = n0 + wn * 32 + ni * 8 + (lane & 3) * 2;
                const size_t o = (size_t)m * CH + j;
                float2 hv = *(float2*)&g_h[o];
                float2 sv = *(float2*)&g_skip[o];
                hv.x += d[0][mi][ni][eh * 2 + 0] + bsm[j];
                hv.y += d[0][mi][ni][eh * 2 + 1] + bsm[j + 1];
                sv.x += d[1][mi][ni][eh * 2 + 0] + bsm[256 + j];
                sv.y += d[1][mi][ni][eh * 2 + 1] + bsm[256 + j + 1];
                *(float2*)&g_h[o] = hv;
                float2 ht; ht.x = rtf(hv.x); ht.y = rtf(hv.y);
                *(float2*)&g_hT[o] = ht;
                *(float2*)&g_skip[o] = sv;
            }
        }
    }
}

// ---------------------------------------------------------------------------
// last layer: skip += acts @ res_last_w + res_last_b (N=256, single half)
// ---------------------------------------------------------------------------
__global__ void __launch_bounds__(256, 2) layerL_mma(const float* __restrict__ rl_b) {
    extern __shared__ char smem[];
    const uint32_t sbase = smem_u32(smem);
    const int tid = threadIdx.x;
    const int lane = tid & 31;
    const int wid = tid >> 5;
    const int wm = wid & 3;
    const int wn = wid >> 2;
    const int row0 = blockIdx.x * 128;
    const int n0 = blockIdx.y * 64;

    {
        float* bsm = (float*)(smem + OFF_BIAS);
        bsm[tid] = rl_b[tid];
    }

    auto load_stage = [&](int s, int buf) {
        const int kk0 = s * 32;
        const uint32_t abase = sbase + OFF_A(buf);
        const uint32_t bbase = sbase + OFF_B(buf);
        #pragma unroll
        for (int i = 0; i < 4; i++) {
            int v = tid + i * 256;
            int row = v >> 3, c8 = v & 7;
            const float* src = g_acts + (size_t)(row0 + row) * CH + kk0 + c8 * 4;
            CP16(abase + row * 144 + c8 * 16, src, 16);
        }
        #pragma unroll
        for (int i = 0; i < 2; i++) {
            int v = tid + i * 256;
            int nl = v >> 3, c8 = v & 7;   // nl 0..63
            const float* src = g_wTL + (size_t)(n0 + nl) * 256 + kk0 + c8 * 4;
            CP16(bbase + nl * 144 + c8 * 16, src, 16);
        }
        CP_COMMIT();
    };

    float d[2][2][4][4] = {};

    load_stage(0, 0);
    for (int s = 0; s < 8; s++) {
        if (s + 1 < 8) { load_stage(s + 1, (s + 1) & 1); CP_WAIT(1); }
        else CP_WAIT(0);
        __syncthreads();
        compute_stage((const float*)(smem + OFF_A(s & 1)),
                      (const float*)(smem + OFF_B(s & 1)), wm, wn, lane, d, 1);
        __syncthreads();
    }

    const float* bsm = (const float*)(smem + OFF_BIAS);
    #pragma unroll
    for (int mi = 0; mi < 2; mi++) {
        #pragma unroll
        for (int eh = 0; eh < 2; eh++) {
            const int m = row0 + wm * 32 + mi * 16 + (lane >> 2) + eh * 8;
            #pragma unroll
            for (int ni = 0; ni < 4; ni++) {
                const int j = n0 + wn * 32 + ni * 8 + (lane & 3) * 2;
                const size_t o = (size_t)m * CH + j;
                float2 sv = *(float2*)&g_skip[o];
                sv.x += d[0][mi][ni][eh * 2 + 0] + bsm[j];
                sv.y += d[0][mi][ni][eh * 2 + 1] + bsm[j + 1];
                *(float2*)&g_skip[o] = sv;
            }
        }
    }
}

// ---------------------------------------------------------------------------
// end: out = skip @ end_w + end_b
// ---------------------------------------------------------------------------
__global__ void end_kernel(const float* __restrict__ ew,
                           const float* __restrict__ eb,
                           float* __restrict__ out) {
    int idx = blockIdx.x * blockDim.x + threadIdx.x;
    int t = idx >> 3;
    int o = idx & 7;
    const float* s = &g_skip[(size_t)t * CH];
    float acc = eb[o];
    #pragma unroll 4
    for (int c = 0; c < CH; c++) acc += s[c] * ew[c * 8 + o];
    out[idx] = acc;
}

// ---------------------------------------------------------------------------
extern "C" void kernel_launch(void* const* d_in, const int* in_sizes, int n_in,
                              void* d_out, int out_size) {
    const float* audio      = (const float*)d_in[0];
    const float* spect      = (const float*)d_in[1];
    const float* start_w    = (const float*)d_in[2];
    const float* start_b    = (const float*)d_in[3];
    const float* in_w       = (const float*)d_in[4];
    const float* in_b       = (const float*)d_in[5];
    const float* cond_w     = (const float*)d_in[6];
    const float* cond_b     = (const float*)d_in[7];
    const float* res_skip_w = (const float*)d_in[8];
    const float* res_skip_b = (const float*)d_in[9];
    const float* res_last_w = (const float*)d_in[10];
    const float* res_last_b = (const float*)d_in[11];
    const float* end_w      = (const float*)d_in[12];
    const float* end_b      = (const float*)d_in[13];
    float* out = (float*)d_out;

    static int attr_done = 0;
    if (!attr_done) {
        cudaFuncSetAttribute(layerA_mma, cudaFuncAttributeMaxDynamicSharedMemorySize, SMEM_SZ);
        cudaFuncSetAttribute(layerB_mma, cudaFuncAttributeMaxDynamicSharedMemorySize, SMEM_SZ);
        cudaFuncSetAttribute(layerL_mma, cudaFuncAttributeMaxDynamicSharedMemorySize, SMEM_SZ);
        attr_done = 1;
    }

    start_kernel<<<(T_TOTAL * CH) / 256, 256>>>(audio, start_w, start_b);
    round_spect_kernel<<<(T_TOTAL / 256) * MEL, 256>>>(spect);
    transA_kernel<<<22528, 256>>>(in_w, cond_w);
    transB_kernel<<<3584, 256>>>(res_skip_w);
    transL_kernel<<<256, 256>>>(res_last_w);

    dim3 g(512, 4);
    for (int l = 0; l < 8; l++) {
        layerA_mma<<<g, 256, SMEM_SZ>>>(in_b, cond_b, l, 1 << l);
        if (l < 7)
            layerB_mma<<<g, 256, SMEM_SZ>>>(res_skip_b, l);
        else
            layerL_mma<<<g, 256, SMEM_SZ>>>(res_last_b);
    }

    end_kernel<<<(T_TOTAL * 8) / 256, 256>>>(end_w, end_b, out);
}